// round 14
// baseline (speedup 1.0000x reference)
#include <cuda_runtime.h>
#include <cuda_fp16.h>
#include <cstdint>
#include <cfloat>

#define NPTS 1536
#define TLEN 20
#define HDIM 64
#define EDIM 16
#define MDIM 128
#define IPB  8              // i's per block (one per warp)
#define JC   32             // j rows per chunk
#define NCHUNK 48
#define JSPLIT 3
#define CPB (NCHUNK / JSPLIT)   // 16 chunks
#define NPAIR (CPB / 2)         // 8 pairs
#define THREADS 256
#define APITCH 144          // halves per smem row (72 words == 8 mod 32: LDS.64 conflict-free)
#define ABUF_BYTES (JC * APITCH * 2)            // 9216
#define OFF_W2 (6 * ABUF_BYTES)                 // 55296
#define SMEM_SZ (OFF_W2 + 16384)                // 71680 (w2c = 1024 x uint4)

// scratch (__device__ globals). A/B stored k-PERMUTED (mperm); W2 as paired frags.
__device__ __half g_Ah[NPTS * MDIM];
__device__ __half g_Bh[NPTS * MDIM];
__device__ uint4  g_W2c[8 * 4 * 32];    // [ks][htp][lane] = {b0,b1}(ht even),{b0,b1}(ht odd)

// Permutation within each 16-k group so mma A fragment halves are contiguous:
__host__ __device__ __forceinline__ int mperm(int m) {
    int g = m >> 4, w = m & 15;
    int pos = (w < 8) ? ((w >> 1) * 4 + (w & 1))
                      : (((w - 8) >> 1) * 4 + 2 + (w & 1));
    return g * 16 + pos;
}

// ---------------------------------------------------------------------------
// Precompute: grid = NPTS/8 = 192 blocks x 128 threads; 8 j's per block with
// W1 staged ONCE in smem (kills the 61MB W1 re-read). Also builds the W2c
// paired-fragment table (blocks 0..7) and zeroes out.
// ---------------------------------------------------------------------------
__global__ void __launch_bounds__(128)
prep_kernel(const float* __restrict__ hidden,
            const float* __restrict__ gt,
            const float* __restrict__ We,
            const float* __restrict__ be,
            const float* __restrict__ W1,
            const float* __restrict__ b1,
            const float* __restrict__ W2,
            float* __restrict__ out) {
    __shared__ float W1s[(HDIM + EDIM) * MDIM];   // 40 KB
    __shared__ float hs[8][HDIM];
    __shared__ float ev[8][2];

    const int jb = blockIdx.x * 8;
    const int m  = threadIdx.x;        // 0..127

    for (int idx = m; idx < (HDIM + EDIM) * MDIM; idx += 128) W1s[idx] = W1[idx];
    for (int idx = m; idx < 8 * HDIM; idx += 128)
        hs[idx >> 6][idx & 63] = hidden[(jb + (idx >> 6)) * HDIM + (idx & 63)];
    if (m < 16)
        ev[m >> 1][m & 1] = gt[((jb + (m >> 1)) * TLEN + (TLEN - 1)) * 2 + (m & 1)];
    __syncthreads();

    // j-invariant terms: P[0,m], P[1,m], q[m]
    float p0 = 0.f, p1 = 0.f, qv = 0.f;
#pragma unroll
    for (int e = 0; e < EDIM; e++) {
        float wv = W1s[(HDIM + e) * MDIM + m];
        p0 += We[e] * wv;
        p1 += We[EDIM + e] * wv;
        qv += be[e] * wv;
    }
    // s[jj] = hidden[jb+jj] @ W1[:,m]
    float s[8];
#pragma unroll
    for (int jj = 0; jj < 8; jj++) s[jj] = 0.f;
#pragma unroll 8
    for (int h = 0; h < HDIM; h++) {
        float wv = W1s[h * MDIM + m];
#pragma unroll
        for (int jj = 0; jj < 8; jj++) s[jj] += hs[jj][h] * wv;
    }

    const int mp = mperm(m);
    const float bb = b1[m];
#pragma unroll
    for (int jj = 0; jj < 8; jj++) {
        float d = ev[jj][0] * p0 + ev[jj][1] * p1;
        g_Bh[(jb + jj) * MDIM + mp] = __float2half(d);
        g_Ah[(jb + jj) * MDIM + mp] = __float2half(s[jj] + d + qv + bb);
    }

    // zero output (atomicMax base): 8 j x 64 h per block
    for (int idx = m; idx < 8 * HDIM; idx += 128) out[jb * HDIM + idx] = 0.f;

    // blocks 0..7 build the paired W2 fragment table (ks = blockIdx.x)
    if (blockIdx.x < 8) {
        int ks  = blockIdx.x;
        int htp = m >> 5;              // 0..3
        int ln  = m & 31;
        int fr  = ln >> 2, fc = ln & 3;
        int k0  = ks * 16 + 2 * fc;    // W2 is (M,H)=(128,64) row-major
        int n0  = (2 * htp) * 8 + fr;
        int n1  = n0 + 8;
        __half2 x  = __floats2half2_rn(W2[k0 * HDIM + n0],       W2[(k0 + 1) * HDIM + n0]);
        __half2 y  = __floats2half2_rn(W2[(k0 + 8) * HDIM + n0], W2[(k0 + 9) * HDIM + n0]);
        __half2 z  = __floats2half2_rn(W2[k0 * HDIM + n1],       W2[(k0 + 1) * HDIM + n1]);
        __half2 w4 = __floats2half2_rn(W2[(k0 + 8) * HDIM + n1], W2[(k0 + 9) * HDIM + n1]);
        uint4 v;
        v.x = *(uint32_t*)&x; v.y = *(uint32_t*)&y;
        v.z = *(uint32_t*)&z; v.w = *(uint32_t*)&w4;
        g_W2c[(ks * 4 + htp) * 32 + ln] = v;
    }
}

// ---------------------------------------------------------------------------
// Main: grid = 576 blocks, 256 threads (8 warps, warp = i). R13 body with
// (a) warp-staggered chunk order within each pair, (b) mid-pair cp.async
// staging so the LDGSTS burst overlaps compute instead of the barrier rush.
// ---------------------------------------------------------------------------
__global__ void __launch_bounds__(THREADS, 2)
main_kernel(const float* __restrict__ b2, float* __restrict__ out) {
    extern __shared__ __align__(16) char smem[];
    uint4* w2c = (uint4*)(smem + OFF_W2);       // [1024]

    const int tid  = threadIdx.x;
    const int w    = tid >> 5;
    const int lane = tid & 31;
    const int ig   = blockIdx.x / JSPLIT;
    const int js   = blockIdx.x % JSPLIT;
    const int i    = ig * IPB + w;
    const int jc0  = js * CPB;

    const int fr = lane >> 2;          // fragment row (0..7)
    const int fc = lane & 3;           // fragment k-quad (0..3)

    // ---- stage A chunk jc into buffer buf (512 x 16B segs, 2 iters) ----
    auto stageA = [&](int buf, int jc) {
        const __half* src = g_Ah + jc * JC * MDIM;
        char* base = smem + buf * ABUF_BYTES;
#pragma unroll
        for (int k = 0; k < 2; k++) {
            int idx = tid + k * THREADS;                   // 0..511
            int row = idx >> 4, seg = idx & 15;
            uint32_t dst = (uint32_t)__cvta_generic_to_shared(
                base + (row * APITCH + seg * 8) * 2);
            asm volatile("cp.async.ca.shared.global [%0], [%1], 16;"
                         :: "r"(dst), "l"(src + idx * 8) : "memory");
        }
    };

    // ---- prologue: w2c (1024 uint4, 4 iters) + pair0 -> G0; pair1 -> G1 ----
#pragma unroll
    for (int k = 0; k < 4; k++) {
        int idx = tid + k * THREADS;                       // 0..1023
        uint32_t dst = (uint32_t)__cvta_generic_to_shared(&w2c[idx]);
        asm volatile("cp.async.ca.shared.global [%0], [%1], 16;"
                     :: "r"(dst), "l"(&g_W2c[idx]) : "memory");
    }
    stageA(0, jc0 + 0); stageA(1, jc0 + 1);
    asm volatile("cp.async.commit_group;" ::: "memory");
    stageA(2, jc0 + 2); stageA(3, jc0 + 3);
    asm volatile("cp.async.commit_group;" ::: "memory");

    // ---- B[i] fragments ----
    __half2 bf[8][2];
#pragma unroll
    for (int ks = 0; ks < 8; ks++) {
        uint2 bv = *(const uint2*)&g_Bh[i * MDIM + ks * 16 + fc * 4];
        bf[ks][0] = *(__half2*)&bv.x;
        bf[ks][1] = *(__half2*)&bv.y;
    }

    float mx[8][2];
#pragma unroll
    for (int t = 0; t < 8; t++) { mx[t][0] = -FLT_MAX; mx[t][1] = -FLT_MAX; }

    const __half2 zero2 = __float2half2_rn(0.f);
    const int wpar = w & 1;             // warp stagger parity

    // ---- mainloop: pairs of chunks, one barrier per pair, 3-pair buffer ring
#pragma unroll 1
    for (int p = 0; p < NPAIR; p++) {
        if (p < NPAIR - 1) {
            asm volatile("cp.async.wait_group 1;" ::: "memory");
        } else {
            asm volatile("cp.async.wait_group 0;" ::: "memory");
        }
        __syncthreads();                // pair p visible; pair p-1 bufs reusable
        int pm3 = p % 3;

        // ---- compute both chunks (single body instance; staggered order) ----
#pragma unroll 1
        for (int q = 0; q < 2; q++) {
            const __half* As = (const __half*)(smem + (2 * pm3 + (q ^ wpar)) * ABUF_BYTES);
            float acc[2][8][4];
#pragma unroll
            for (int jt = 0; jt < 2; jt++)
#pragma unroll
                for (int ht = 0; ht < 8; ht++)
#pragma unroll
                    for (int r = 0; r < 4; r++) acc[jt][ht][r] = 0.f;

#pragma unroll
            for (int ks = 0; ks < 8; ks++) {
                const int koff = ks * 16 + fc * 4;
                uint32_t za[2][4];
#pragma unroll
                for (int jt = 0; jt < 2; jt++) {
                    uint2 v0 = *(const uint2*)&As[(jt * 16 + fr) * APITCH + koff];     // a0|a2
                    uint2 v1 = *(const uint2*)&As[(jt * 16 + 8 + fr) * APITCH + koff]; // a1|a3
                    __half2 a0 = __hmax2(__hsub2(*(__half2*)&v0.x, bf[ks][0]), zero2);
                    __half2 a2 = __hmax2(__hsub2(*(__half2*)&v0.y, bf[ks][1]), zero2);
                    __half2 a1 = __hmax2(__hsub2(*(__half2*)&v1.x, bf[ks][0]), zero2);
                    __half2 a3 = __hmax2(__hsub2(*(__half2*)&v1.y, bf[ks][1]), zero2);
                    za[jt][0] = *(uint32_t*)&a0;
                    za[jt][1] = *(uint32_t*)&a1;
                    za[jt][2] = *(uint32_t*)&a2;
                    za[jt][3] = *(uint32_t*)&a3;
                }
#pragma unroll
                for (int htp = 0; htp < 4; htp++) {
                    uint4 wv = w2c[(ks * 4 + htp) * 32 + lane];  // one LDS.128, 2 ht tiles
#pragma unroll
                    for (int jt = 0; jt < 2; jt++) {
                        asm volatile(
                            "mma.sync.aligned.m16n8k16.row.col.f32.f16.f16.f32 "
                            "{%0,%1,%2,%3},{%4,%5,%6,%7},{%8,%9},{%0,%1,%2,%3};"
                            : "+f"(acc[jt][2 * htp][0]), "+f"(acc[jt][2 * htp][1]),
                              "+f"(acc[jt][2 * htp][2]), "+f"(acc[jt][2 * htp][3])
                            : "r"(za[jt][0]), "r"(za[jt][1]), "r"(za[jt][2]), "r"(za[jt][3]),
                              "r"(wv.x), "r"(wv.y));
                        asm volatile(
                            "mma.sync.aligned.m16n8k16.row.col.f32.f16.f16.f32 "
                            "{%0,%1,%2,%3},{%4,%5,%6,%7},{%8,%9},{%0,%1,%2,%3};"
                            : "+f"(acc[jt][2 * htp + 1][0]), "+f"(acc[jt][2 * htp + 1][1]),
                              "+f"(acc[jt][2 * htp + 1][2]), "+f"(acc[jt][2 * htp + 1][3])
                            : "r"(za[jt][0]), "r"(za[jt][1]), "r"(za[jt][2]), "r"(za[jt][3]),
                              "r"(wv.z), "r"(wv.w));
                    }
                }
            }
            // fold both j-tiles into running max
#pragma unroll
            for (int jt = 0; jt < 2; jt++)
#pragma unroll
                for (int ht = 0; ht < 8; ht++) {
                    mx[ht][0] = fmaxf(mx[ht][0], fmaxf(acc[jt][ht][0], acc[jt][ht][2]));
                    mx[ht][1] = fmaxf(mx[ht][1], fmaxf(acc[jt][ht][1], acc[jt][ht][3]));
                }

            // mid-pair staging: overlap LDGSTS burst with chunk-q1 compute
            if (q == 0 && p + 2 < NPAIR) {
                int pb2 = pm3 + 2; if (pb2 >= 3) pb2 -= 3;
                stageA(2 * pb2,     jc0 + 2 * p + 4);
                stageA(2 * pb2 + 1, jc0 + 2 * p + 5);
                asm volatile("cp.async.commit_group;" ::: "memory");
            }
        }
    }

    // ---- reduce max across j-row lanes (same h: lane%4 groups) ----
#pragma unroll
    for (int ht = 0; ht < 8; ht++) {
#pragma unroll
        for (int s = 4; s < 32; s <<= 1) {
            mx[ht][0] = fmaxf(mx[ht][0], __shfl_xor_sync(0xffffffffu, mx[ht][0], s));
            mx[ht][1] = fmaxf(mx[ht][1], __shfl_xor_sync(0xffffffffu, mx[ht][1], s));
        }
    }
    if (lane < 4) {
#pragma unroll
        for (int ht = 0; ht < 8; ht++) {
            int h = ht * 8 + 2 * lane;
            float v0 = fmaxf(mx[ht][0] + b2[h], 0.f);
            float v1 = fmaxf(mx[ht][1] + b2[h + 1], 0.f);
            // relu output >= 0: int-ordered atomicMax exact; out pre-zeroed in prep
            atomicMax((int*)&out[i * HDIM + h],     __float_as_int(v0));
            atomicMax((int*)&out[i * HDIM + h + 1], __float_as_int(v1));
        }
    }
}

// ---------------------------------------------------------------------------
extern "C" void kernel_launch(void* const* d_in, const int* in_sizes, int n_in,
                              void* d_out, int out_size) {
    const float* hidden = (const float*)d_in[0];
    const float* gt     = (const float*)d_in[1];
    const float* We     = (const float*)d_in[2];
    const float* be     = (const float*)d_in[3];
    const float* W1     = (const float*)d_in[4];
    const float* b1     = (const float*)d_in[5];
    const float* W2     = (const float*)d_in[6];
    const float* b2     = (const float*)d_in[7];
    float* out = (float*)d_out;

    prep_kernel<<<NPTS / 8, 128>>>(hidden, gt, We, be, W1, b1, W2, out);
    cudaFuncSetAttribute(main_kernel, cudaFuncAttributeMaxDynamicSharedMemorySize, SMEM_SZ);
    main_kernel<<<(NPTS / IPB) * JSPLIT, THREADS, SMEM_SZ>>>(b2, out);
}

// round 15
// speedup vs baseline: 1.0029x; 1.0029x over previous
#include <cuda_runtime.h>
#include <cuda_fp16.h>
#include <cstdint>
#include <cfloat>

#define NPTS 1536
#define TLEN 20
#define HDIM 64
#define EDIM 16
#define MDIM 128
#define IPB  8              // i's per block (one per warp)
#define JC   32             // j rows per chunk
#define NCHUNK 48
#define JSPLIT 3
#define CPB (NCHUNK / JSPLIT)   // 16 chunks
#define NPAIR (CPB / 2)         // 8 pairs
#define THREADS 256
#define APITCH 144          // halves per smem row (72 words == 8 mod 32: LDS.64 conflict-free)
#define ABUF_BYTES (JC * APITCH * 2)            // 9216
#define OFF_W2 (6 * ABUF_BYTES)                 // 55296
#define SMEM_SZ (OFF_W2 + 16384)                // 71680 (w2c = 1024 x uint4)

// scratch (__device__ globals). A/B stored k-PERMUTED (mperm); W2 as paired frags.
__device__ __half g_Ah[NPTS * MDIM];
__device__ __half g_Bh[NPTS * MDIM];
__device__ uint4  g_W2c[8 * 4 * 32];    // [ks][htp][lane] = {b0,b1}(ht even),{b0,b1}(ht odd)

// Permutation within each 16-k group so mma A fragment halves are contiguous:
__host__ __device__ __forceinline__ int mperm(int m) {
    int g = m >> 4, w = m & 15;
    int pos = (w < 8) ? ((w >> 1) * 4 + (w & 1))
                      : (((w - 8) >> 1) * 4 + 2 + (w & 1));
    return g * 16 + pos;
}

// ---------------------------------------------------------------------------
// Precompute: grid = NPTS/8 = 192 blocks x 128 threads; 8 j's per block with
// W1 staged ONCE in smem. Builds W2c paired-fragment table (blocks 0..7),
// zeroes out.
// ---------------------------------------------------------------------------
__global__ void __launch_bounds__(128)
prep_kernel(const float* __restrict__ hidden,
            const float* __restrict__ gt,
            const float* __restrict__ We,
            const float* __restrict__ be,
            const float* __restrict__ W1,
            const float* __restrict__ b1,
            const float* __restrict__ W2,
            float* __restrict__ out) {
    __shared__ float W1s[(HDIM + EDIM) * MDIM];   // 40 KB
    __shared__ float hs[8][HDIM];
    __shared__ float ev[8][2];

    const int jb = blockIdx.x * 8;
    const int m  = threadIdx.x;        // 0..127

    for (int idx = m; idx < (HDIM + EDIM) * MDIM; idx += 128) W1s[idx] = W1[idx];
    for (int idx = m; idx < 8 * HDIM; idx += 128)
        hs[idx >> 6][idx & 63] = hidden[(jb + (idx >> 6)) * HDIM + (idx & 63)];
    if (m < 16)
        ev[m >> 1][m & 1] = gt[((jb + (m >> 1)) * TLEN + (TLEN - 1)) * 2 + (m & 1)];
    __syncthreads();

    float p0 = 0.f, p1 = 0.f, qv = 0.f;
#pragma unroll
    for (int e = 0; e < EDIM; e++) {
        float wv = W1s[(HDIM + e) * MDIM + m];
        p0 += We[e] * wv;
        p1 += We[EDIM + e] * wv;
        qv += be[e] * wv;
    }
    float s[8];
#pragma unroll
    for (int jj = 0; jj < 8; jj++) s[jj] = 0.f;
#pragma unroll 8
    for (int h = 0; h < HDIM; h++) {
        float wv = W1s[h * MDIM + m];
#pragma unroll
        for (int jj = 0; jj < 8; jj++) s[jj] += hs[jj][h] * wv;
    }

    const int mp = mperm(m);
    const float bb = b1[m];
#pragma unroll
    for (int jj = 0; jj < 8; jj++) {
        float d = ev[jj][0] * p0 + ev[jj][1] * p1;
        g_Bh[(jb + jj) * MDIM + mp] = __float2half(d);
        g_Ah[(jb + jj) * MDIM + mp] = __float2half(s[jj] + d + qv + bb);
    }

    for (int idx = m; idx < 8 * HDIM; idx += 128) out[jb * HDIM + idx] = 0.f;

    if (blockIdx.x < 8) {
        int ks  = blockIdx.x;
        int htp = m >> 5;
        int ln  = m & 31;
        int fr  = ln >> 2, fc = ln & 3;
        int k0  = ks * 16 + 2 * fc;    // W2 is (M,H)=(128,64) row-major
        int n0  = (2 * htp) * 8 + fr;
        int n1  = n0 + 8;
        __half2 x  = __floats2half2_rn(W2[k0 * HDIM + n0],       W2[(k0 + 1) * HDIM + n0]);
        __half2 y  = __floats2half2_rn(W2[(k0 + 8) * HDIM + n0], W2[(k0 + 9) * HDIM + n0]);
        __half2 z  = __floats2half2_rn(W2[k0 * HDIM + n1],       W2[(k0 + 1) * HDIM + n1]);
        __half2 w4 = __floats2half2_rn(W2[(k0 + 8) * HDIM + n1], W2[(k0 + 9) * HDIM + n1]);
        uint4 v;
        v.x = *(uint32_t*)&x; v.y = *(uint32_t*)&y;
        v.z = *(uint32_t*)&z; v.w = *(uint32_t*)&w4;
        g_W2c[(ks * 4 + htp) * 32 + ln] = v;
    }
}

// ---------------------------------------------------------------------------
// Main: grid = 576, 256 threads (8 warps, warp = i). R13 structure; HMMA with
// FP16 accumulation in TWO 4-chain sets (ksA=0..3, ksB=4..7), combined per
// chunk via HADD2; j-fold via packed HMAX2.
// ---------------------------------------------------------------------------
__global__ void __launch_bounds__(THREADS, 2)
main_kernel(const float* __restrict__ b2, float* __restrict__ out) {
    extern __shared__ __align__(16) char smem[];
    uint4* w2c = (uint4*)(smem + OFF_W2);       // [1024]

    const int tid  = threadIdx.x;
    const int w    = tid >> 5;
    const int lane = tid & 31;
    const int ig   = blockIdx.x / JSPLIT;
    const int js   = blockIdx.x % JSPLIT;
    const int i    = ig * IPB + w;
    const int jc0  = js * CPB;

    const int fr = lane >> 2;          // fragment row (0..7)
    const int fc = lane & 3;           // fragment k-quad (0..3)

    auto stageA = [&](int buf, int jc) {
        const __half* src = g_Ah + jc * JC * MDIM;
        char* base = smem + buf * ABUF_BYTES;
#pragma unroll
        for (int k = 0; k < 2; k++) {
            int idx = tid + k * THREADS;                   // 0..511
            int row = idx >> 4, seg = idx & 15;
            uint32_t dst = (uint32_t)__cvta_generic_to_shared(
                base + (row * APITCH + seg * 8) * 2);
            asm volatile("cp.async.ca.shared.global [%0], [%1], 16;"
                         :: "r"(dst), "l"(src + idx * 8) : "memory");
        }
    };

    // ---- prologue: w2c (1024 uint4) + pair0 -> G0; pair1 -> G1 ----
#pragma unroll
    for (int k = 0; k < 4; k++) {
        int idx = tid + k * THREADS;
        uint32_t dst = (uint32_t)__cvta_generic_to_shared(&w2c[idx]);
        asm volatile("cp.async.ca.shared.global [%0], [%1], 16;"
                     :: "r"(dst), "l"(&g_W2c[idx]) : "memory");
    }
    stageA(0, jc0 + 0); stageA(1, jc0 + 1);
    asm volatile("cp.async.commit_group;" ::: "memory");
    stageA(2, jc0 + 2); stageA(3, jc0 + 3);
    asm volatile("cp.async.commit_group;" ::: "memory");

    // ---- B[i] fragments ----
    __half2 bf[8][2];
#pragma unroll
    for (int ks = 0; ks < 8; ks++) {
        uint2 bv = *(const uint2*)&g_Bh[i * MDIM + ks * 16 + fc * 4];
        bf[ks][0] = *(__half2*)&bv.x;
        bf[ks][1] = *(__half2*)&bv.y;
    }

    // running max, packed f16x2: mx16[ht] = {max v0, max v1}
    __half2 mx16[8];
#pragma unroll
    for (int t = 0; t < 8; t++) mx16[t] = __float2half2_rn(-60000.f);

    const __half2 zero2 = __float2half2_rn(0.f);

    // ---- mainloop: pairs of chunks, one barrier per pair, 3-pair ring ----
#pragma unroll 1
    for (int p = 0; p < NPAIR; p++) {
        if (p < NPAIR - 1) {
            asm volatile("cp.async.wait_group 1;" ::: "memory");
        } else {
            asm volatile("cp.async.wait_group 0;" ::: "memory");
        }
        __syncthreads();                // pair p visible; pair p-1 bufs reusable
        int pm3 = p % 3;
        if (p + 2 < NPAIR) {
            int pb2 = pm3 + 2; if (pb2 >= 3) pb2 -= 3;
            stageA(2 * pb2,     jc0 + 2 * p + 4);
            stageA(2 * pb2 + 1, jc0 + 2 * p + 5);
            asm volatile("cp.async.commit_group;" ::: "memory");
        }

        // ---- compute both chunks (single body instance) ----
#pragma unroll 1
        for (int q = 0; q < 2; q++) {
            const __half* As = (const __half*)(smem + (2 * pm3 + q) * ABUF_BYTES);
            // f16x2 accumulators: two sets (ks 0-3 / ks 4-7), [jt][ht][reg]
            uint32_t accA[2][8][2], accB[2][8][2];
#pragma unroll
            for (int jt = 0; jt < 2; jt++)
#pragma unroll
                for (int ht = 0; ht < 8; ht++) {
                    accA[jt][ht][0] = 0u; accA[jt][ht][1] = 0u;
                    accB[jt][ht][0] = 0u; accB[jt][ht][1] = 0u;
                }

#pragma unroll
            for (int ks = 0; ks < 8; ks++) {
                const int koff = ks * 16 + fc * 4;
                uint32_t za[2][4];
#pragma unroll
                for (int jt = 0; jt < 2; jt++) {
                    uint2 v0 = *(const uint2*)&As[(jt * 16 + fr) * APITCH + koff];     // a0|a2
                    uint2 v1 = *(const uint2*)&As[(jt * 16 + 8 + fr) * APITCH + koff]; // a1|a3
                    __half2 a0 = __hmax2(__hsub2(*(__half2*)&v0.x, bf[ks][0]), zero2);
                    __half2 a2 = __hmax2(__hsub2(*(__half2*)&v0.y, bf[ks][1]), zero2);
                    __half2 a1 = __hmax2(__hsub2(*(__half2*)&v1.x, bf[ks][0]), zero2);
                    __half2 a3 = __hmax2(__hsub2(*(__half2*)&v1.y, bf[ks][1]), zero2);
                    za[jt][0] = *(uint32_t*)&a0;
                    za[jt][1] = *(uint32_t*)&a1;
                    za[jt][2] = *(uint32_t*)&a2;
                    za[jt][3] = *(uint32_t*)&a3;
                }
                uint32_t (*acc)[8][2] = (ks < 4) ? accA : accB;   // static (ks unrolled)
#pragma unroll
                for (int htp = 0; htp < 4; htp++) {
                    uint4 wv = w2c[(ks * 4 + htp) * 32 + lane];   // one LDS.128, 2 ht tiles
#pragma unroll
                    for (int jt = 0; jt < 2; jt++) {
                        asm volatile(
                            "mma.sync.aligned.m16n8k16.row.col.f16.f16.f16.f16 "
                            "{%0,%1},{%2,%3,%4,%5},{%6,%7},{%0,%1};"
                            : "+r"(acc[jt][2 * htp][0]), "+r"(acc[jt][2 * htp][1])
                            : "r"(za[jt][0]), "r"(za[jt][1]), "r"(za[jt][2]), "r"(za[jt][3]),
                              "r"(wv.x), "r"(wv.y));
                        asm volatile(
                            "mma.sync.aligned.m16n8k16.row.col.f16.f16.f16.f16 "
                            "{%0,%1},{%2,%3,%4,%5},{%6,%7},{%0,%1};"
                            : "+r"(acc[jt][2 * htp + 1][0]), "+r"(acc[jt][2 * htp + 1][1])
                            : "r"(za[jt][0]), "r"(za[jt][1]), "r"(za[jt][2]), "r"(za[jt][3]),
                              "r"(wv.z), "r"(wv.w));
                    }
                }
            }
            // combine sets (f32-safe 4-chains) + fold j rows via packed HMAX2
#pragma unroll
            for (int jt = 0; jt < 2; jt++)
#pragma unroll
                for (int ht = 0; ht < 8; ht++) {
                    __half2 c0 = __hadd2(*(__half2*)&accA[jt][ht][0], *(__half2*)&accB[jt][ht][0]);
                    __half2 c1 = __hadd2(*(__half2*)&accA[jt][ht][1], *(__half2*)&accB[jt][ht][1]);
                    mx16[ht] = __hmax2(mx16[ht], __hmax2(c0, c1));  // {max(c0,c2),max(c1,c3)}
                }
        }
    }

    // ---- reduce max across j-row lanes (same h: lane%4 groups), packed ----
#pragma unroll
    for (int ht = 0; ht < 8; ht++) {
#pragma unroll
        for (int s = 4; s < 32; s <<= 1) {
            uint32_t v = __shfl_xor_sync(0xffffffffu, *(uint32_t*)&mx16[ht], s);
            mx16[ht] = __hmax2(mx16[ht], *(__half2*)&v);
        }
    }
    if (lane < 4) {
#pragma unroll
        for (int ht = 0; ht < 8; ht++) {
            int h = ht * 8 + 2 * lane;
            float v0 = fmaxf(__low2float(mx16[ht])  + b2[h],     0.f);
            float v1 = fmaxf(__high2float(mx16[ht]) + b2[h + 1], 0.f);
            // relu output >= 0: int-ordered atomicMax exact; out pre-zeroed in prep
            atomicMax((int*)&out[i * HDIM + h],     __float_as_int(v0));
            atomicMax((int*)&out[i * HDIM + h + 1], __float_as_int(v1));
        }
    }
}

// ---------------------------------------------------------------------------
extern "C" void kernel_launch(void* const* d_in, const int* in_sizes, int n_in,
                              void* d_out, int out_size) {
    const float* hidden = (const float*)d_in[0];
    const float* gt     = (const float*)d_in[1];
    const float* We     = (const float*)d_in[2];
    const float* be     = (const float*)d_in[3];
    const float* W1     = (const float*)d_in[4];
    const float* b1     = (const float*)d_in[5];
    const float* W2     = (const float*)d_in[6];
    const float* b2     = (const float*)d_in[7];
    float* out = (float*)d_out;

    prep_kernel<<<NPTS / 8, 128>>>(hidden, gt, We, be, W1, b1, W2, out);
    cudaFuncSetAttribute(main_kernel, cudaFuncAttributeMaxDynamicSharedMemorySize, SMEM_SZ);
    main_kernel<<<(NPTS / IPB) * JSPLIT, THREADS, SMEM_SZ>>>(b2, out);
}

// round 16
// speedup vs baseline: 1.0236x; 1.0207x over previous
#include <cuda_runtime.h>
#include <cuda_fp16.h>
#include <cstdint>
#include <cfloat>

#define NPTS 1536
#define TLEN 20
#define HDIM 64
#define EDIM 16
#define MDIM 128
#define IPB  8              // i's per block (one per warp)
#define JC   32             // j rows per chunk
#define NCHUNK 48
#define JSPLIT 3
#define CPB (NCHUNK / JSPLIT)   // 16 chunks
#define GSZ  4                  // chunks per barrier group
#define NG   (CPB / GSZ)        // 4 groups
#define THREADS 256
#define APITCH 144          // halves per smem row (72 words == 8 mod 32: LDS.64 conflict-free)
#define ABUF_BYTES (JC * APITCH * 2)            // 9216
#define OFF_W2 (8 * ABUF_BYTES)                 // 73728
#define SMEM_SZ (OFF_W2 + 16384)                // 90112 (w2c = 1024 x uint4)

// scratch (__device__ globals). A/B stored k-PERMUTED (mperm); W2 as paired frags.
__device__ __half g_Ah[NPTS * MDIM];
__device__ __half g_Bh[NPTS * MDIM];
__device__ uint4  g_W2c[8 * 4 * 32];    // [ks][htp][lane] = {b0,b1}(ht even),{b0,b1}(ht odd)

// Permutation within each 16-k group so mma A fragment halves are contiguous:
__host__ __device__ __forceinline__ int mperm(int m) {
    int g = m >> 4, w = m & 15;
    int pos = (w < 8) ? ((w >> 1) * 4 + (w & 1))
                      : (((w - 8) >> 1) * 4 + 2 + (w & 1));
    return g * 16 + pos;
}

// ---------------------------------------------------------------------------
// Precompute: grid = NPTS/8 = 192 blocks x 128 threads; 8 j's per block with
// W1 staged ONCE in smem. Builds W2c paired-fragment table (blocks 0..7),
// zeroes out.
// ---------------------------------------------------------------------------
__global__ void __launch_bounds__(128)
prep_kernel(const float* __restrict__ hidden,
            const float* __restrict__ gt,
            const float* __restrict__ We,
            const float* __restrict__ be,
            const float* __restrict__ W1,
            const float* __restrict__ b1,
            const float* __restrict__ W2,
            float* __restrict__ out) {
    __shared__ float W1s[(HDIM + EDIM) * MDIM];   // 40 KB
    __shared__ float hs[8][HDIM];
    __shared__ float ev[8][2];

    const int jb = blockIdx.x * 8;
    const int m  = threadIdx.x;        // 0..127

    for (int idx = m; idx < (HDIM + EDIM) * MDIM; idx += 128) W1s[idx] = W1[idx];
    for (int idx = m; idx < 8 * HDIM; idx += 128)
        hs[idx >> 6][idx & 63] = hidden[(jb + (idx >> 6)) * HDIM + (idx & 63)];
    if (m < 16)
        ev[m >> 1][m & 1] = gt[((jb + (m >> 1)) * TLEN + (TLEN - 1)) * 2 + (m & 1)];
    __syncthreads();

    float p0 = 0.f, p1 = 0.f, qv = 0.f;
#pragma unroll
    for (int e = 0; e < EDIM; e++) {
        float wv = W1s[(HDIM + e) * MDIM + m];
        p0 += We[e] * wv;
        p1 += We[EDIM + e] * wv;
        qv += be[e] * wv;
    }
    float s[8];
#pragma unroll
    for (int jj = 0; jj < 8; jj++) s[jj] = 0.f;
#pragma unroll 8
    for (int h = 0; h < HDIM; h++) {
        float wv = W1s[h * MDIM + m];
#pragma unroll
        for (int jj = 0; jj < 8; jj++) s[jj] += hs[jj][h] * wv;
    }

    const int mp = mperm(m);
    const float bb = b1[m];
#pragma unroll
    for (int jj = 0; jj < 8; jj++) {
        float d = ev[jj][0] * p0 + ev[jj][1] * p1;
        g_Bh[(jb + jj) * MDIM + mp] = __float2half(d);
        g_Ah[(jb + jj) * MDIM + mp] = __float2half(s[jj] + d + qv + bb);
    }

    for (int idx = m; idx < 8 * HDIM; idx += 128) out[jb * HDIM + idx] = 0.f;

    if (blockIdx.x < 8) {
        int ks  = blockIdx.x;
        int htp = m >> 5;
        int ln  = m & 31;
        int fr  = ln >> 2, fc = ln & 3;
        int k0  = ks * 16 + 2 * fc;    // W2 is (M,H)=(128,64) row-major
        int n0  = (2 * htp) * 8 + fr;
        int n1  = n0 + 8;
        __half2 x  = __floats2half2_rn(W2[k0 * HDIM + n0],       W2[(k0 + 1) * HDIM + n0]);
        __half2 y  = __floats2half2_rn(W2[(k0 + 8) * HDIM + n0], W2[(k0 + 9) * HDIM + n0]);
        __half2 z  = __floats2half2_rn(W2[k0 * HDIM + n1],       W2[(k0 + 1) * HDIM + n1]);
        __half2 w4 = __floats2half2_rn(W2[(k0 + 8) * HDIM + n1], W2[(k0 + 9) * HDIM + n1]);
        uint4 v;
        v.x = *(uint32_t*)&x; v.y = *(uint32_t*)&y;
        v.z = *(uint32_t*)&z; v.w = *(uint32_t*)&w4;
        g_W2c[(ks * 4 + htp) * 32 + ln] = v;
    }
}

// ---------------------------------------------------------------------------
// Main: grid = 576, 256 threads (8 warps, warp = i). R13 f32 body; groups of
// 4 chunks per barrier, 2-group buffer ring (depth-1 group pipelining).
// ---------------------------------------------------------------------------
__global__ void __launch_bounds__(THREADS, 2)
main_kernel(const float* __restrict__ b2, float* __restrict__ out) {
    extern __shared__ __align__(16) char smem[];
    uint4* w2c = (uint4*)(smem + OFF_W2);       // [1024]

    const int tid  = threadIdx.x;
    const int w    = tid >> 5;
    const int lane = tid & 31;
    const int ig   = blockIdx.x / JSPLIT;
    const int js   = blockIdx.x % JSPLIT;
    const int i    = ig * IPB + w;
    const int jc0  = js * CPB;

    const int fr = lane >> 2;          // fragment row (0..7)
    const int fc = lane & 3;           // fragment k-quad (0..3)

    // ---- stage A chunk jc into buffer buf (512 x 16B segs, 2 iters) ----
    auto stageA = [&](int buf, int jc) {
        const __half* src = g_Ah + jc * JC * MDIM;
        char* base = smem + buf * ABUF_BYTES;
#pragma unroll
        for (int k = 0; k < 2; k++) {
            int idx = tid + k * THREADS;                   // 0..511
            int row = idx >> 4, seg = idx & 15;
            uint32_t dst = (uint32_t)__cvta_generic_to_shared(
                base + (row * APITCH + seg * 8) * 2);
            asm volatile("cp.async.ca.shared.global [%0], [%1], 16;"
                         :: "r"(dst), "l"(src + idx * 8) : "memory");
        }
    };

    // ---- prologue: w2c (1024 uint4) + group 0 (chunks 0..3) in ONE group ----
#pragma unroll
    for (int k = 0; k < 4; k++) {
        int idx = tid + k * THREADS;
        uint32_t dst = (uint32_t)__cvta_generic_to_shared(&w2c[idx]);
        asm volatile("cp.async.ca.shared.global [%0], [%1], 16;"
                     :: "r"(dst), "l"(&g_W2c[idx]) : "memory");
    }
#pragma unroll
    for (int q = 0; q < GSZ; q++) stageA(q, jc0 + q);
    asm volatile("cp.async.commit_group;" ::: "memory");

    // ---- B[i] fragments ----
    __half2 bf[8][2];
#pragma unroll
    for (int ks = 0; ks < 8; ks++) {
        uint2 bv = *(const uint2*)&g_Bh[i * MDIM + ks * 16 + fc * 4];
        bf[ks][0] = *(__half2*)&bv.x;
        bf[ks][1] = *(__half2*)&bv.y;
    }

    float mx[8][2];
#pragma unroll
    for (int t = 0; t < 8; t++) { mx[t][0] = -FLT_MAX; mx[t][1] = -FLT_MAX; }

    const __half2 zero2 = __float2half2_rn(0.f);

    // ---- mainloop: groups of 4 chunks, ONE barrier per group ----
#pragma unroll 1
    for (int g = 0; g < NG; g++) {
        asm volatile("cp.async.wait_group 0;" ::: "memory");
        __syncthreads();                // group g visible; other half free
        const int gb = (g & 1) * GSZ;   // this group's buffer base
        if (g + 1 < NG) {               // stage next group into the other half
            const int nb = ((g + 1) & 1) * GSZ;
#pragma unroll
            for (int q = 0; q < GSZ; q++) stageA(nb + q, jc0 + (g + 1) * GSZ + q);
            asm volatile("cp.async.commit_group;" ::: "memory");
        }

        // ---- compute 4 chunks (single body instance) ----
#pragma unroll 1
        for (int q = 0; q < GSZ; q++) {
            const __half* As = (const __half*)(smem + (gb + q) * ABUF_BYTES);
            float acc[2][8][4];
#pragma unroll
            for (int jt = 0; jt < 2; jt++)
#pragma unroll
                for (int ht = 0; ht < 8; ht++)
#pragma unroll
                    for (int r = 0; r < 4; r++) acc[jt][ht][r] = 0.f;

#pragma unroll
            for (int ks = 0; ks < 8; ks++) {
                const int koff = ks * 16 + fc * 4;
                uint32_t za[2][4];
#pragma unroll
                for (int jt = 0; jt < 2; jt++) {
                    uint2 v0 = *(const uint2*)&As[(jt * 16 + fr) * APITCH + koff];     // a0|a2
                    uint2 v1 = *(const uint2*)&As[(jt * 16 + 8 + fr) * APITCH + koff]; // a1|a3
                    __half2 a0 = __hmax2(__hsub2(*(__half2*)&v0.x, bf[ks][0]), zero2);
                    __half2 a2 = __hmax2(__hsub2(*(__half2*)&v0.y, bf[ks][1]), zero2);
                    __half2 a1 = __hmax2(__hsub2(*(__half2*)&v1.x, bf[ks][0]), zero2);
                    __half2 a3 = __hmax2(__hsub2(*(__half2*)&v1.y, bf[ks][1]), zero2);
                    za[jt][0] = *(uint32_t*)&a0;
                    za[jt][1] = *(uint32_t*)&a1;
                    za[jt][2] = *(uint32_t*)&a2;
                    za[jt][3] = *(uint32_t*)&a3;
                }
#pragma unroll
                for (int htp = 0; htp < 4; htp++) {
                    uint4 wv = w2c[(ks * 4 + htp) * 32 + lane];  // one LDS.128, 2 ht tiles
#pragma unroll
                    for (int jt = 0; jt < 2; jt++) {
                        asm volatile(
                            "mma.sync.aligned.m16n8k16.row.col.f32.f16.f16.f32 "
                            "{%0,%1,%2,%3},{%4,%5,%6,%7},{%8,%9},{%0,%1,%2,%3};"
                            : "+f"(acc[jt][2 * htp][0]), "+f"(acc[jt][2 * htp][1]),
                              "+f"(acc[jt][2 * htp][2]), "+f"(acc[jt][2 * htp][3])
                            : "r"(za[jt][0]), "r"(za[jt][1]), "r"(za[jt][2]), "r"(za[jt][3]),
                              "r"(wv.x), "r"(wv.y));
                        asm volatile(
                            "mma.sync.aligned.m16n8k16.row.col.f32.f16.f16.f32 "
                            "{%0,%1,%2,%3},{%4,%5,%6,%7},{%8,%9},{%0,%1,%2,%3};"
                            : "+f"(acc[jt][2 * htp + 1][0]), "+f"(acc[jt][2 * htp + 1][1]),
                              "+f"(acc[jt][2 * htp + 1][2]), "+f"(acc[jt][2 * htp + 1][3])
                            : "r"(za[jt][0]), "r"(za[jt][1]), "r"(za[jt][2]), "r"(za[jt][3]),
                              "r"(wv.z), "r"(wv.w));
                    }
                }
            }
            // fold both j-tiles into running max
#pragma unroll
            for (int jt = 0; jt < 2; jt++)
#pragma unroll
                for (int ht = 0; ht < 8; ht++) {
                    mx[ht][0] = fmaxf(mx[ht][0], fmaxf(acc[jt][ht][0], acc[jt][ht][2]));
                    mx[ht][1] = fmaxf(mx[ht][1], fmaxf(acc[jt][ht][1], acc[jt][ht][3]));
                }
        }
    }

    // ---- reduce max across j-row lanes (same h: lane%4 groups) ----
#pragma unroll
    for (int ht = 0; ht < 8; ht++) {
#pragma unroll
        for (int s = 4; s < 32; s <<= 1) {
            mx[ht][0] = fmaxf(mx[ht][0], __shfl_xor_sync(0xffffffffu, mx[ht][0], s));
            mx[ht][1] = fmaxf(mx[ht][1], __shfl_xor_sync(0xffffffffu, mx[ht][1], s));
        }
    }
    if (lane < 4) {
#pragma unroll
        for (int ht = 0; ht < 8; ht++) {
            int h = ht * 8 + 2 * lane;
            float v0 = fmaxf(mx[ht][0] + b2[h], 0.f);
            float v1 = fmaxf(mx[ht][1] + b2[h + 1], 0.f);
            // relu output >= 0: int-ordered atomicMax exact; out pre-zeroed in prep
            atomicMax((int*)&out[i * HDIM + h],     __float_as_int(v0));
            atomicMax((int*)&out[i * HDIM + h + 1], __float_as_int(v1));
        }
    }
}

// ---------------------------------------------------------------------------
extern "C" void kernel_launch(void* const* d_in, const int* in_sizes, int n_in,
                              void* d_out, int out_size) {
    const float* hidden = (const float*)d_in[0];
    const float* gt     = (const float*)d_in[1];
    const float* We     = (const float*)d_in[2];
    const float* be     = (const float*)d_in[3];
    const float* W1     = (const float*)d_in[4];
    const float* b1     = (const float*)d_in[5];
    const float* W2     = (const float*)d_in[6];
    const float* b2     = (const float*)d_in[7];
    float* out = (float*)d_out;

    prep_kernel<<<NPTS / 8, 128>>>(hidden, gt, We, be, W1, b1, W2, out);
    cudaFuncSetAttribute(main_kernel, cudaFuncAttributeMaxDynamicSharedMemorySize, SMEM_SZ);
    main_kernel<<<(NPTS / IPB) * JSPLIT, THREADS, SMEM_SZ>>>(b2, out);
}